// round 15
// baseline (speedup 1.0000x reference)
#include <cuda_runtime.h>
#include <cuda_bf16.h>
#include <math.h>
#include <stdint.h>
#include <algorithm>

// Problem dims (fixed by setup_inputs)
#define DB    4
#define DS    2048
#define DD    2048          // model dim
#define DE    8             // experts
#define DH    5632          // hidden dim
#define DT    (DB*DS)       // 8192 tokens
#define KTOP  2
#define NSLOT (DT*KTOP)         // 16384 (token,expert) rows
#define MAXSLOT (NSLOT + DE*64) // 16896, per-expert 64-aligned padding
#define MAXMT (MAXSLOT/64)      // 264 m-tiles max
#define NSPR  256               // MAX_SPR_TOKENS

// ---------------- device scratch (static allocs only, per harness rules) ----
__device__ float g_G[(size_t)MAXSLOT * DH];   // silu(x@w1)*(x@w2)
__device__ float g_O[(size_t)MAXSLOT * DD];   // expert outputs
__device__ float g_probs[DT * DE];
__device__ float g_topw[DT * KTOP];
__device__ int   g_tope[DT * KTOP];
__device__ int   g_rowof[DT * KTOP];
__device__ int   g_token_list[MAXSLOT];
__device__ int   g_counts[DE];
__device__ int   g_cursor[DE];
__device__ int   g_off[DE];
__device__ int   g_tile_expert[MAXMT];
__device__ int   g_num_mtiles;
__device__ float g_Psum[DE];
// SPR scratch
__device__ float g_xn[NSPR * DD];
__device__ float g_rn[NSPR * DE];
__device__ float g_spr_part[NSPR];

struct IdxArr { int v[NSPR]; };

// ---------------- reset (graph replays reuse device globals) ----------------
__global__ void reset_kernel() {
    int i = blockIdx.x * blockDim.x + threadIdx.x;
    if (i < MAXSLOT) g_token_list[i] = -1;
    if (i < DE) { g_counts[i] = 0; g_Psum[i] = 0.f; }
}

// ---------------- router: logits, softmax, top-2, counts --------------------
__global__ __launch_bounds__(256) void router_kernel(
    const float* __restrict__ x, const float* __restrict__ gw) {
    __shared__ float sgw[DE][256];
    int tid  = threadIdx.x;
    int lane = tid & 31;
    int w    = tid >> 5;
    int tok  = blockIdx.x * 8 + w;

    const float* xr = x + (size_t)tok * DD;
    float acc[DE];
#pragma unroll
    for (int e = 0; e < DE; e++) acc[e] = 0.f;

    for (int k0 = 0; k0 < DD; k0 += 256) {
#pragma unroll
        for (int i = 0; i < 8; i++) {
            int idx = tid + i * 256;
            int e = idx >> 8, k = idx & 255;
            sgw[e][k] = gw[e * DD + k0 + k];
        }
        __syncthreads();
        for (int k = lane; k < 256; k += 32) {
            float xv = xr[k0 + k];
#pragma unroll
            for (int e = 0; e < DE; e++) acc[e] += xv * sgw[e][k];
        }
        __syncthreads();
    }
#pragma unroll
    for (int e = 0; e < DE; e++)
#pragma unroll
        for (int o = 16; o > 0; o >>= 1)
            acc[e] += __shfl_xor_sync(0xffffffffu, acc[e], o);

    if (lane == 0) {
        float m = acc[0];
#pragma unroll
        for (int e = 1; e < DE; e++) m = fmaxf(m, acc[e]);
        float p[DE], s = 0.f;
#pragma unroll
        for (int e = 0; e < DE; e++) { p[e] = expf(acc[e] - m); s += p[e]; }
        float inv = 1.f / s;
#pragma unroll
        for (int e = 0; e < DE; e++) { p[e] *= inv; g_probs[tok * DE + e] = p[e]; }
        int e0 = 0;
#pragma unroll
        for (int e = 1; e < DE; e++) if (p[e] > p[e0]) e0 = e;
        int e1 = (e0 == 0) ? 1 : 0;
#pragma unroll
        for (int e = 0; e < DE; e++) if (e != e0 && p[e] > p[e1]) e1 = e;
        float denom = 1.f / (p[e0] + p[e1]);
        g_tope[tok * 2 + 0] = e0;  g_topw[tok * 2 + 0] = p[e0] * denom;
        g_tope[tok * 2 + 1] = e1;  g_topw[tok * 2 + 1] = p[e1] * denom;
        atomicAdd(&g_counts[e0], 1);
        atomicAdd(&g_counts[e1], 1);
    }
}

// ---------------- plan: aligned offsets + tile->expert map ------------------
__global__ void plan_kernel() {
    if (threadIdx.x == 0 && blockIdx.x == 0) {
        int off = 0, mt = 0;
        for (int e = 0; e < DE; e++) {
            g_off[e] = off;
            g_cursor[e] = 0;
            int nt = (g_counts[e] + 63) >> 6;
            for (int i = 0; i < nt; i++) g_tile_expert[mt + i] = e;
            mt  += nt;
            off += nt * 64;
        }
        g_num_mtiles = mt;
    }
}

// ---------------- assign: token -> slot --------------------------------------
__global__ void assign_kernel() {
    int t = blockIdx.x * blockDim.x + threadIdx.x;
    if (t >= DT) return;
#pragma unroll
    for (int k = 0; k < KTOP; k++) {
        int e = g_tope[t * 2 + k];
        int pos = atomicAdd(&g_cursor[e], 1);
        int slot = g_off[e] + pos;
        g_token_list[slot] = t;
        g_rowof[t * 2 + k] = slot;
    }
}

// ---------------- P_i deterministic reduction --------------------------------
__global__ void preduce_kernel() {
    int e = blockIdx.x;
    __shared__ float sm[256];
    float s = 0.f;
    for (int t = threadIdx.x; t < DT; t += 256) s += g_probs[t * DE + e];
    sm[threadIdx.x] = s;
    __syncthreads();
    for (int o = 128; o > 0; o >>= 1) {
        if (threadIdx.x < o) sm[threadIdx.x] += sm[threadIdx.x + o];
        __syncthreads();
    }
    if (threadIdx.x == 0) g_Psum[e] = sm[0];
}

// ================= 3xTF32 mma.sync building blocks ==========================
__device__ __forceinline__ void split_tf32(float v, uint32_t& hi, uint32_t& lo) {
    uint32_t h;
    asm("cvt.rna.tf32.f32 %0, %1;" : "=r"(h) : "f"(v));
    float l = v - __uint_as_float(h);
    asm("cvt.rna.tf32.f32 %0, %1;" : "=r"(lo) : "f"(l));
    hi = h;
}

__device__ __forceinline__ void mma_tf32(float* c, const uint32_t* a, const uint32_t* b) {
    asm volatile(
        "mma.sync.aligned.m16n8k8.row.col.f32.tf32.tf32.f32 "
        "{%0,%1,%2,%3}, {%4,%5,%6,%7}, {%8,%9}, {%0,%1,%2,%3};"
        : "+f"(c[0]), "+f"(c[1]), "+f"(c[2]), "+f"(c[3])
        : "r"(a[0]), "r"(a[1]), "r"(a[2]), "r"(a[3]), "r"(b[0]), "r"(b[1]));
}

// ---------------- fused GEMM1: G = silu(X@W1) * (X@W2) ----------------------
// 64x128 tile, 8 warps (2x4), warp tile 32x32 = 2x4 m16n8k8 fragments.
// 3xTF32 split: hi*hi + hi*lo + lo*hi per mma site -> ~fp32 accuracy.
#define BM 64
#define BN 128
#define BK 16
#define BMP 72      // A smem pitch: 72%32=8 -> conflict-free fragment LDS
#define BNP 136     // B smem pitch: 136%32=8 -> conflict-free fragment LDS
__global__ __launch_bounds__(256) void gemm1_kernel(
    const float* __restrict__ x,
    const float* __restrict__ w1, const float* __restrict__ w2) {
    int tile_m = blockIdx.y;
    if (tile_m >= g_num_mtiles) return;
    int e = g_tile_expert[tile_m];
    int slot0 = tile_m * BM;
    int n0 = blockIdx.x * BN;
    const float* B1 = w1 + (size_t)e * DD * DH;
    const float* B2 = w2 + (size_t)e * DD * DH;

    __shared__ float As[2][BK][BMP];
    __shared__ float Bs1[2][BK][BNP];
    __shared__ float Bs2[2][BK][BNP];
    __shared__ int toks[BM];

    int tid = threadIdx.x;
    if (tid < BM) toks[tid] = g_token_list[slot0 + tid];
    __syncthreads();

    int lane = tid & 31;
    int wid  = tid >> 5;
    int wm = wid & 1;        // 2 warp rows  (32 M each)
    int wn = wid >> 1;       // 4 warp cols  (32 N each)
    int gr = lane >> 2;      // fragment group row (0..7)
    int gc = lane & 3;       // fragment group col (0..3)

    // loader coords (same as verified double-buffered layout)
    int am = tid >> 4, ak = tid & 15;
    int br0 = tid >> 7, bc = tid & 127;

    float rA[4], rB1[8], rB2[8];
    float C1[2][4][4], C2[2][4][4];
#pragma unroll
    for (int mi = 0; mi < 2; mi++)
#pragma unroll
        for (int ni = 0; ni < 4; ni++)
#pragma unroll
            for (int q = 0; q < 4; q++) { C1[mi][ni][q] = 0.f; C2[mi][ni][q] = 0.f; }

    // prologue: load k0=0 tile
#pragma unroll
    for (int i = 0; i < 4; i++) {
        int t = toks[am + i * 16];
        rA[i] = (t >= 0) ? x[(size_t)t * DD + ak] : 0.f;
    }
#pragma unroll
    for (int i = 0; i < 8; i++) {
        int r = br0 + i * 2;
        size_t g = (size_t)r * DH + n0 + bc;
        rB1[i] = B1[g];
        rB2[i] = B2[g];
    }
#pragma unroll
    for (int i = 0; i < 4; i++) As[0][ak][am + i * 16] = rA[i];
#pragma unroll
    for (int i = 0; i < 8; i++) { Bs1[0][br0 + i * 2][bc] = rB1[i]; Bs2[0][br0 + i * 2][bc] = rB2[i]; }
    __syncthreads();

    int buf = 0;
    for (int k0 = 0; k0 < DD; k0 += BK) {
        bool has_next = (k0 + BK) < DD;
        if (has_next) {
            int kn = k0 + BK;
#pragma unroll
            for (int i = 0; i < 4; i++) {
                int t = toks[am + i * 16];
                rA[i] = (t >= 0) ? x[(size_t)t * DD + kn + ak] : 0.f;
            }
#pragma unroll
            for (int i = 0; i < 8; i++) {
                int r = br0 + i * 2;
                size_t g = (size_t)(kn + r) * DH + n0 + bc;
                rB1[i] = B1[g];
                rB2[i] = B2[g];
            }
        }
        // compute: 2 k-sub-chunks of 8
#pragma unroll
        for (int ks = 0; ks < BK; ks += 8) {
            // A fragments (2 m-tiles), split hi/lo
            uint32_t ahi[2][4], alo[2][4];
#pragma unroll
            for (int mi = 0; mi < 2; mi++) {
                int mb = wm * 32 + mi * 16;
                float f0 = As[buf][ks + gc    ][mb + gr];
                float f1 = As[buf][ks + gc    ][mb + gr + 8];
                float f2 = As[buf][ks + gc + 4][mb + gr];
                float f3 = As[buf][ks + gc + 4][mb + gr + 8];
                split_tf32(f0, ahi[mi][0], alo[mi][0]);
                split_tf32(f1, ahi[mi][1], alo[mi][1]);
                split_tf32(f2, ahi[mi][2], alo[mi][2]);
                split_tf32(f3, ahi[mi][3], alo[mi][3]);
            }
            // B1 fragments (4 n-tiles), then C1 mmas
            {
                uint32_t bh[4][2], bl[4][2];
#pragma unroll
                for (int ni = 0; ni < 4; ni++) {
                    int nb = wn * 32 + ni * 8;
                    float f0 = Bs1[buf][ks + gc    ][nb + gr];
                    float f1 = Bs1[buf][ks + gc + 4][nb + gr];
                    split_tf32(f0, bh[ni][0], bl[ni][0]);
                    split_tf32(f1, bh[ni][1], bl[ni][1]);
                }
#pragma unroll
                for (int mi = 0; mi < 2; mi++)
#pragma unroll
                    for (int ni = 0; ni < 4; ni++) {
                        mma_tf32(C1[mi][ni], ahi[mi], bh[ni]);
                        mma_tf32(C1[mi][ni], ahi[mi], bl[ni]);
                        mma_tf32(C1[mi][ni], alo[mi], bh[ni]);
                    }
            }
            // B2 fragments, C2 mmas (reuses frag registers)
            {
                uint32_t bh[4][2], bl[4][2];
#pragma unroll
                for (int ni = 0; ni < 4; ni++) {
                    int nb = wn * 32 + ni * 8;
                    float f0 = Bs2[buf][ks + gc    ][nb + gr];
                    float f1 = Bs2[buf][ks + gc + 4][nb + gr];
                    split_tf32(f0, bh[ni][0], bl[ni][0]);
                    split_tf32(f1, bh[ni][1], bl[ni][1]);
                }
#pragma unroll
                for (int mi = 0; mi < 2; mi++)
#pragma unroll
                    for (int ni = 0; ni < 4; ni++) {
                        mma_tf32(C2[mi][ni], ahi[mi], bh[ni]);
                        mma_tf32(C2[mi][ni], ahi[mi], bl[ni]);
                        mma_tf32(C2[mi][ni], alo[mi], bh[ni]);
                    }
            }
        }
        if (has_next) {
            int nb = buf ^ 1;
#pragma unroll
            for (int i = 0; i < 4; i++) As[nb][ak][am + i * 16] = rA[i];
#pragma unroll
            for (int i = 0; i < 8; i++) { Bs1[nb][br0 + i * 2][bc] = rB1[i]; Bs2[nb][br0 + i * 2][bc] = rB2[i]; }
            __syncthreads();
            buf = nb;
        }
    }
    // epilogue: silu(c1)*c2 -> g_G
#pragma unroll
    for (int mi = 0; mi < 2; mi++)
#pragma unroll
        for (int ni = 0; ni < 4; ni++) {
            int r0 = slot0 + wm * 32 + mi * 16 + gr;
            int cb = n0 + wn * 32 + ni * 8 + gc * 2;
            float* c1 = C1[mi][ni];
            float* c2 = C2[mi][ni];
            float s0 = c1[0] / (1.f + expf(-c1[0]));
            float s1 = c1[1] / (1.f + expf(-c1[1]));
            float s2 = c1[2] / (1.f + expf(-c1[2]));
            float s3 = c1[3] / (1.f + expf(-c1[3]));
            g_G[(size_t)r0 * DH + cb]           = s0 * c2[0];
            g_G[(size_t)r0 * DH + cb + 1]       = s1 * c2[1];
            g_G[(size_t)(r0 + 8) * DH + cb]     = s2 * c2[2];
            g_G[(size_t)(r0 + 8) * DH + cb + 1] = s3 * c2[3];
        }
}

// ---------------- GEMM2: O = G @ W3  (same structure, single B) -------------
__global__ __launch_bounds__(256) void gemm2_kernel(const float* __restrict__ w3) {
    int tile_m = blockIdx.y;
    if (tile_m >= g_num_mtiles) return;
    int e = g_tile_expert[tile_m];
    int slot0 = tile_m * BM;
    int n0 = blockIdx.x * BN;
    const float* Bw = w3 + (size_t)e * DH * DD;

    __shared__ float As[2][BK][BMP];
    __shared__ float Bs[2][BK][BNP];

    int tid = threadIdx.x;
    int lane = tid & 31;
    int wid  = tid >> 5;
    int wm = wid & 1;
    int wn = wid >> 1;
    int gr = lane >> 2;
    int gc = lane & 3;
    int am = tid >> 4, ak = tid & 15;
    int br0 = tid >> 7, bc = tid & 127;

    float rA[4], rB[8];
    float C[2][4][4];
#pragma unroll
    for (int mi = 0; mi < 2; mi++)
#pragma unroll
        for (int ni = 0; ni < 4; ni++)
#pragma unroll
            for (int q = 0; q < 4; q++) C[mi][ni][q] = 0.f;

    // prologue
#pragma unroll
    for (int i = 0; i < 4; i++)
        rA[i] = g_G[(size_t)(slot0 + am + i * 16) * DH + ak];
#pragma unroll
    for (int i = 0; i < 8; i++) {
        int r = br0 + i * 2;
        rB[i] = Bw[(size_t)r * DD + n0 + bc];
    }
#pragma unroll
    for (int i = 0; i < 4; i++) As[0][ak][am + i * 16] = rA[i];
#pragma unroll
    for (int i = 0; i < 8; i++) Bs[0][br0 + i * 2][bc] = rB[i];
    __syncthreads();

    int buf = 0;
    for (int k0 = 0; k0 < DH; k0 += BK) {
        bool has_next = (k0 + BK) < DH;
        if (has_next) {
            int kn = k0 + BK;
#pragma unroll
            for (int i = 0; i < 4; i++)
                rA[i] = g_G[(size_t)(slot0 + am + i * 16) * DH + kn + ak];
#pragma unroll
            for (int i = 0; i < 8; i++) {
                int r = br0 + i * 2;
                rB[i] = Bw[(size_t)(kn + r) * DD + n0 + bc];
            }
        }
#pragma unroll
        for (int ks = 0; ks < BK; ks += 8) {
            uint32_t ahi[2][4], alo[2][4];
#pragma unroll
            for (int mi = 0; mi < 2; mi++) {
                int mb = wm * 32 + mi * 16;
                float f0 = As[buf][ks + gc    ][mb + gr];
                float f1 = As[buf][ks + gc    ][mb + gr + 8];
                float f2 = As[buf][ks + gc + 4][mb + gr];
                float f3 = As[buf][ks + gc + 4][mb + gr + 8];
                split_tf32(f0, ahi[mi][0], alo[mi][0]);
                split_tf32(f1, ahi[mi][1], alo[mi][1]);
                split_tf32(f2, ahi[mi][2], alo[mi][2]);
                split_tf32(f3, ahi[mi][3], alo[mi][3]);
            }
            uint32_t bh[4][2], bl[4][2];
#pragma unroll
            for (int ni = 0; ni < 4; ni++) {
                int nb = wn * 32 + ni * 8;
                float f0 = Bs[buf][ks + gc    ][nb + gr];
                float f1 = Bs[buf][ks + gc + 4][nb + gr];
                split_tf32(f0, bh[ni][0], bl[ni][0]);
                split_tf32(f1, bh[ni][1], bl[ni][1]);
            }
#pragma unroll
            for (int mi = 0; mi < 2; mi++)
#pragma unroll
                for (int ni = 0; ni < 4; ni++) {
                    mma_tf32(C[mi][ni], ahi[mi], bh[ni]);
                    mma_tf32(C[mi][ni], ahi[mi], bl[ni]);
                    mma_tf32(C[mi][ni], alo[mi], bh[ni]);
                }
        }
        if (has_next) {
            int nb = buf ^ 1;
#pragma unroll
            for (int i = 0; i < 4; i++) As[nb][ak][am + i * 16] = rA[i];
#pragma unroll
            for (int i = 0; i < 8; i++) Bs[nb][br0 + i * 2][bc] = rB[i];
            __syncthreads();
            buf = nb;
        }
    }
#pragma unroll
    for (int mi = 0; mi < 2; mi++)
#pragma unroll
        for (int ni = 0; ni < 4; ni++) {
            int r0 = slot0 + wm * 32 + mi * 16 + gr;
            int cb = n0 + wn * 32 + ni * 8 + gc * 2;
            float* c = C[mi][ni];
            g_O[(size_t)r0 * DD + cb]           = c[0];
            g_O[(size_t)r0 * DD + cb + 1]       = c[1];
            g_O[(size_t)(r0 + 8) * DD + cb]     = c[2];
            g_O[(size_t)(r0 + 8) * DD + cb + 1] = c[3];
        }
}

// ---------------- combine (atomic-free, deterministic) ----------------------
__global__ void combine_kernel(float* __restrict__ out) {
    size_t i = (size_t)blockIdx.x * blockDim.x + threadIdx.x;
    const size_t total4 = (size_t)DT * DD / 4;
    if (i >= total4) return;
    int t = (int)(i / (DD / 4));
    int dg = (int)(i % (DD / 4));
    int r0 = g_rowof[t * 2 + 0], r1 = g_rowof[t * 2 + 1];
    float w0 = g_topw[t * 2 + 0], w1 = g_topw[t * 2 + 1];
    float4 a = reinterpret_cast<const float4*>(g_O + (size_t)r0 * DD)[dg];
    float4 b = reinterpret_cast<const float4*>(g_O + (size_t)r1 * DD)[dg];
    float4 o;
    o.x = w0 * a.x + w1 * b.x;
    o.y = w0 * a.y + w1 * b.y;
    o.z = w0 * a.z + w1 * b.z;
    o.w = w0 * a.w + w1 * b.w;
    reinterpret_cast<float4*>(out)[i] = o;
}

// ---------------- SPR prep: gather + row-normalize x and probs rows ---------
__global__ __launch_bounds__(256) void spr_prep_kernel(
    const float* __restrict__ x, IdxArr idx) {
    int i = blockIdx.x;           // 0..255 subsampled row
    int t = idx.v[i];
    const float* xr = x + (size_t)t * DD;
    __shared__ float sm[256];
    __shared__ float s_inv;
    float s = 0.f;
    for (int k = threadIdx.x; k < DD; k += 256) { float v = xr[k]; s += v * v; }
    sm[threadIdx.x] = s;
    __syncthreads();
    for (int o = 128; o > 0; o >>= 1) {
        if (threadIdx.x < o) sm[threadIdx.x] += sm[threadIdx.x + o];
        __syncthreads();
    }
    if (threadIdx.x == 0) {
        s_inv = 1.f / fmaxf(sqrtf(sm[0]), 1e-12f);
        float pr[DE], ps = 0.f;
#pragma unroll
        for (int e = 0; e < DE; e++) { pr[e] = g_probs[t * DE + e]; ps += pr[e] * pr[e]; }
        float pinv = 1.f / fmaxf(sqrtf(ps), 1e-12f);
#pragma unroll
        for (int e = 0; e < DE; e++) g_rn[i * DE + e] = pr[e] * pinv;
    }
    __syncthreads();
    float inv = s_inv;
    for (int k = threadIdx.x; k < DD; k += 256) g_xn[(size_t)i * DD + k] = xr[k] * inv;
}

// ---------------- SPR gram diff: block i computes row i of both grams -------
__global__ __launch_bounds__(256) void spr_gram_kernel() {
    int i = blockIdx.x;           // 0..255
    __shared__ float xi[DD];      // 8 KB
    __shared__ float ri[DE];
    __shared__ float sm[256];
    for (int k = threadIdx.x; k < DD; k += 256) xi[k] = g_xn[(size_t)i * DD + k];
    if (threadIdx.x < DE) ri[threadIdx.x] = g_rn[i * DE + threadIdx.x];
    __syncthreads();
    int j = threadIdx.x;
    float dx = 0.f;
    const float* xj = g_xn + (size_t)j * DD;
    for (int k = 0; k < DD; k++) dx += xi[k] * xj[k];
    float dr = 0.f;
#pragma unroll
    for (int e = 0; e < DE; e++) dr += ri[e] * g_rn[j * DE + e];
    float d = dr - dx;
    sm[threadIdx.x] = d * d;
    __syncthreads();
    for (int o = 128; o > 0; o >>= 1) {
        if (threadIdx.x < o) sm[threadIdx.x] += sm[threadIdx.x + o];
        __syncthreads();
    }
    if (threadIdx.x == 0) g_spr_part[i] = sm[0];
}

// ---------------- aux loss: load_balance + dpsl + 0.1*spr -------------------
__global__ void aux_kernel(float* __restrict__ out, int out_size) {
    if (threadIdx.x == 0 && blockIdx.x == 0) {
        float lb = 0.f, dpsl = 0.f;
        const float prior = 0.125f;
        const float logp  = logf(prior);
        for (int e = 0; e < DE; e++) {
            float f = (float)g_counts[e] / (float)(DT * KTOP);
            float P = g_Psum[e] / (float)DT;
            lb += f * P;
            dpsl += prior * (logp - logf(P));
        }
        lb *= (float)DE;
        float sprs = 0.f;
        for (int i = 0; i < NSPR; i++) sprs += g_spr_part[i];
        float spr = sprs / (float)(NSPR * NSPR);
        float aux = 0.01f * (lb + dpsl + 0.1f * spr);
        for (size_t i = (size_t)DT * DD; i < (size_t)out_size; i++) out[i] = aux;
    }
}

// ============================================================================
// Host-side replication of jax.random.permutation(jax.random.key(123), 8192)
// Input-independent: runs once at graph-capture time, zero cost in replays.
// ============================================================================
static inline uint32_t rotl32h(uint32_t x, int r) { return (x << r) | (x >> (32 - r)); }

static void threefry2x32_host(uint32_t k1, uint32_t k2, uint32_t x1, uint32_t x2,
                              uint32_t* o1, uint32_t* o2) {
    uint32_t ks0 = k1, ks1 = k2, ks2 = k1 ^ k2 ^ 0x1BD11BDAu;
    uint32_t ks[3] = {ks0, ks1, ks2};
    uint32_t a = x1 + ks0, b = x2 + ks1;
    static const int R[2][4] = {{13, 15, 26, 6}, {17, 29, 16, 24}};
    for (int i = 0; i < 5; i++) {
        const int* r = R[i & 1];
        for (int j = 0; j < 4; j++) { a += b; b = rotl32h(b, r[j]); b ^= a; }
        a += ks[(i + 1) % 3];
        b += ks[(i + 2) % 3] + (uint32_t)(i + 1);
    }
    *o1 = a; *o2 = b;
}

// split(key) -> (new_key, subkey): threefry on counts [0,1,2,3] paired (0,2),(1,3)
static void jax_split_host(const uint32_t key[2], uint32_t newkey[2], uint32_t subkey[2]) {
    uint32_t a0, b0, a1, b1;
    threefry2x32_host(key[0], key[1], 0u, 2u, &a0, &b0);
    threefry2x32_host(key[0], key[1], 1u, 3u, &a1, &b1);
    newkey[0] = a0; newkey[1] = a1;
    subkey[0] = b0; subkey[1] = b1;
}

static void compute_spr_indices(int* idx_out) {
    const int T = DT;             // 8192
    static uint32_t bits[DT];
    static int vals[DT];
    static int order[DT];
    static int tmp[DT];
    for (int i = 0; i < T; i++) vals[i] = i;

    uint32_t key[2] = {0u, 123u};     // jax.random.key(123) -> (0, 123)
    for (int round = 0; round < 2; round++) {   // num_rounds = 2 for T=8192
        uint32_t nk[2], sk[2];
        jax_split_host(key, nk, sk);
        key[0] = nk[0]; key[1] = nk[1];
        // random_bits(subkey, 32, (8192,)): pairs (i, i+4096)
        for (int i = 0; i < T / 2; i++) {
            uint32_t o1, o2;
            threefry2x32_host(sk[0], sk[1], (uint32_t)i, (uint32_t)(i + T / 2), &o1, &o2);
            bits[i] = o1;
            bits[i + T / 2] = o2;
        }
        // stable sort by bits, carrying vals (matches lax.sort_key_val)
        for (int i = 0; i < T; i++) order[i] = i;
        std::stable_sort(order, order + T,
                         [](int a, int b) { return bits[a] < bits[b]; });
        for (int i = 0; i < T; i++) tmp[i] = vals[order[i]];
        for (int i = 0; i < T; i++) vals[i] = tmp[i];
    }
    for (int i = 0; i < NSPR; i++) idx_out[i] = vals[i];
}

// ---------------- launch ----------------------------------------------------
extern "C" void kernel_launch(void* const* d_in, const int* in_sizes, int n_in,
                              void* d_out, int out_size) {
    const float* x  = (const float*)d_in[0];
    const float* gw = (const float*)d_in[1];
    const float* w1 = (const float*)d_in[2];
    const float* w2 = (const float*)d_in[3];
    const float* w3 = (const float*)d_in[4];
    float* out = (float*)d_out;

    IdxArr idx;
    compute_spr_indices(idx.v);   // pure host compute; deterministic

    reset_kernel<<<(MAXSLOT + 255) / 256, 256>>>();
    router_kernel<<<DT / 8, 256>>>(x, gw);
    plan_kernel<<<1, 32>>>();
    assign_kernel<<<(DT + 255) / 256, 256>>>();
    preduce_kernel<<<DE, 256>>>();

    dim3 g1(DH / BN, MAXMT);     // 44 x 264
    gemm1_kernel<<<g1, 256>>>(x, w1, w2);
    dim3 g2(DD / BN, MAXMT);     // 16 x 264
    gemm2_kernel<<<g2, 256>>>(w3);

    const size_t total4 = (size_t)DT * DD / 4;
    combine_kernel<<<(unsigned)((total4 + 255) / 256), 256>>>(out);

    spr_prep_kernel<<<NSPR, 256>>>(x, idx);
    spr_gram_kernel<<<NSPR, 256>>>();
    aux_kernel<<<1, 32>>>(out, out_size);
}

// round 16
// speedup vs baseline: 1.7582x; 1.7582x over previous
#include <cuda_runtime.h>
#include <cuda_bf16.h>
#include <math.h>
#include <stdint.h>
#include <algorithm>

// Problem dims (fixed by setup_inputs)
#define DB    4
#define DS    2048
#define DD    2048          // model dim
#define DE    8             // experts
#define DH    5632          // hidden dim
#define DT    (DB*DS)       // 8192 tokens
#define KTOP  2
#define NSLOT (DT*KTOP)         // 16384 (token,expert) rows
#define MAXSLOT (NSLOT + DE*64) // 16896, per-expert 64-aligned padding
#define MAXMT (MAXSLOT/64)      // 264 m-tiles max
#define NSPR  256               // MAX_SPR_TOKENS

// ---------------- device scratch (static allocs only, per harness rules) ----
__device__ float g_G[(size_t)MAXSLOT * DH];   // silu(x@w1)*(x@w2)
__device__ float g_O[(size_t)MAXSLOT * DD];   // expert outputs
__device__ float g_probs[DT * DE];
__device__ float g_topw[DT * KTOP];
__device__ int   g_tope[DT * KTOP];
__device__ int   g_rowof[DT * KTOP];
__device__ int   g_token_list[MAXSLOT];
__device__ int   g_counts[DE];
__device__ int   g_cursor[DE];
__device__ int   g_tile_expert[MAXMT];
__device__ int   g_num_mtiles;
__device__ float g_Psum[DE];
// SPR scratch
__device__ float g_xn[NSPR * DD];
__device__ float g_rn[NSPR * DE];
__device__ float g_spr_part[NSPR];

struct IdxArr { int v[NSPR]; };

// ---------------- reset (graph replays reuse device globals) ----------------
__global__ void reset_kernel() {
    int i = blockIdx.x * blockDim.x + threadIdx.x;
    if (i < MAXSLOT) g_token_list[i] = -1;
    if (i < DE) { g_counts[i] = 0; g_cursor[i] = 0; g_Psum[i] = 0.f; }
}

// ---------------- router: logits, softmax, top-2, counts --------------------
__global__ __launch_bounds__(256) void router_kernel(
    const float* __restrict__ x, const float* __restrict__ gw) {
    __shared__ float sgw[DE][256];
    int tid  = threadIdx.x;
    int lane = tid & 31;
    int w    = tid >> 5;
    int tok  = blockIdx.x * 8 + w;

    const float* xr = x + (size_t)tok * DD;
    float acc[DE];
#pragma unroll
    for (int e = 0; e < DE; e++) acc[e] = 0.f;

    for (int k0 = 0; k0 < DD; k0 += 256) {
#pragma unroll
        for (int i = 0; i < 8; i++) {
            int idx = tid + i * 256;
            int e = idx >> 8, k = idx & 255;
            sgw[e][k] = gw[e * DD + k0 + k];
        }
        __syncthreads();
        for (int k = lane; k < 256; k += 32) {
            float xv = xr[k0 + k];
#pragma unroll
            for (int e = 0; e < DE; e++) acc[e] += xv * sgw[e][k];
        }
        __syncthreads();
    }
#pragma unroll
    for (int e = 0; e < DE; e++)
#pragma unroll
        for (int o = 16; o > 0; o >>= 1)
            acc[e] += __shfl_xor_sync(0xffffffffu, acc[e], o);

    if (lane == 0) {
        float m = acc[0];
#pragma unroll
        for (int e = 1; e < DE; e++) m = fmaxf(m, acc[e]);
        float p[DE], s = 0.f;
#pragma unroll
        for (int e = 0; e < DE; e++) { p[e] = expf(acc[e] - m); s += p[e]; }
        float inv = 1.f / s;
#pragma unroll
        for (int e = 0; e < DE; e++) { p[e] *= inv; g_probs[tok * DE + e] = p[e]; }
        int e0 = 0;
#pragma unroll
        for (int e = 1; e < DE; e++) if (p[e] > p[e0]) e0 = e;
        int e1 = (e0 == 0) ? 1 : 0;
#pragma unroll
        for (int e = 0; e < DE; e++) if (e != e0 && p[e] > p[e1]) e1 = e;
        float denom = 1.f / (p[e0] + p[e1]);
        g_tope[tok * 2 + 0] = e0;  g_topw[tok * 2 + 0] = p[e0] * denom;
        g_tope[tok * 2 + 1] = e1;  g_topw[tok * 2 + 1] = p[e1] * denom;
        atomicAdd(&g_counts[e0], 1);
        atomicAdd(&g_counts[e1], 1);
    }
}

// ---------------- assign+plan merged (keeps gemm1 at launch idx 3) ----------
// Each block recomputes the tiny 8-expert prefix locally; block 0 also writes
// the tile->expert map. Identical results to the verified plan+assign pair.
__global__ void assign_plan_kernel() {
    __shared__ int soff[DE];
    if (threadIdx.x == 0) {
        int off = 0;
        for (int e = 0; e < DE; e++) {
            soff[e] = off;
            off += ((g_counts[e] + 63) >> 6) * 64;
        }
        if (blockIdx.x == 0) {
            int mt = 0;
            for (int e = 0; e < DE; e++) {
                int nt = (g_counts[e] + 63) >> 6;
                for (int i = 0; i < nt; i++) g_tile_expert[mt + i] = e;
                mt += nt;
            }
            g_num_mtiles = mt;
        }
    }
    __syncthreads();
    int t = blockIdx.x * blockDim.x + threadIdx.x;
    if (t >= DT) return;
#pragma unroll
    for (int k = 0; k < KTOP; k++) {
        int e = g_tope[t * 2 + k];
        int pos = atomicAdd(&g_cursor[e], 1);
        int slot = soff[e] + pos;
        g_token_list[slot] = t;
        g_rowof[t * 2 + k] = slot;
    }
}

// ---------------- P_i deterministic reduction --------------------------------
__global__ void preduce_kernel() {
    int e = blockIdx.x;
    __shared__ float sm[256];
    float s = 0.f;
    for (int t = threadIdx.x; t < DT; t += 256) s += g_probs[t * DE + e];
    sm[threadIdx.x] = s;
    __syncthreads();
    for (int o = 128; o > 0; o >>= 1) {
        if (threadIdx.x < o) sm[threadIdx.x] += sm[threadIdx.x + o];
        __syncthreads();
    }
    if (threadIdx.x == 0) g_Psum[e] = sm[0];
}

// ================= 3xBF16 mma.sync building blocks ==========================
// Split v = hi + lo in bf16; packed pairs (elem k in low half, k+1 in high).
// 3 terms hi*hi + hi*lo + lo*hi -> ~1e-5 relative accuracy (lo*lo ~2^-18).
__device__ __forceinline__ void split_bf16x2(float f0, float f1,
                                             uint32_t& hi, uint32_t& lo) {
    uint32_t h;
    asm("cvt.rn.bf16x2.f32 %0, %1, %2;" : "=r"(h) : "f"(f1), "f"(f0));
    float h0 = __uint_as_float(h << 16);
    float h1 = __uint_as_float(h & 0xffff0000u);
    float l0 = f0 - h0;
    float l1 = f1 - h1;
    asm("cvt.rn.bf16x2.f32 %0, %1, %2;" : "=r"(lo) : "f"(l1), "f"(l0));
    hi = h;
}

__device__ __forceinline__ void mma_bf16(float* c, const uint32_t* a, const uint32_t* b) {
    asm volatile(
        "mma.sync.aligned.m16n8k16.row.col.f32.bf16.bf16.f32 "
        "{%0,%1,%2,%3}, {%4,%5,%6,%7}, {%8,%9}, {%0,%1,%2,%3};"
        : "+f"(c[0]), "+f"(c[1]), "+f"(c[2]), "+f"(c[3])
        : "r"(a[0]), "r"(a[1]), "r"(a[2]), "r"(a[3]), "r"(b[0]), "r"(b[1]));
}

// ---------------- fused GEMM1: G = silu(X@W1) * (X@W2) ----------------------
// 64x128 tile, 8 warps (2x4), warp tile 32x32 = 2x4 m16n8k16 fragments.
#define BM 64
#define BN 128
#define BK 16
#define BMP 68      // pitch%16==4 -> stride-2gc k rows hit distinct banks
#define BNP 132     // pitch%16==4 -> same property for B
__global__ __launch_bounds__(256) void gemm1_kernel(
    const float* __restrict__ x,
    const float* __restrict__ w1, const float* __restrict__ w2) {
    int tile_m = blockIdx.y;
    if (tile_m >= g_num_mtiles) return;
    int e = g_tile_expert[tile_m];
    int slot0 = tile_m * BM;
    int n0 = blockIdx.x * BN;
    const float* B1 = w1 + (size_t)e * DD * DH;
    const float* B2 = w2 + (size_t)e * DD * DH;

    __shared__ float As[2][BK][BMP];
    __shared__ float Bs1[2][BK][BNP];
    __shared__ float Bs2[2][BK][BNP];
    __shared__ int toks[BM];

    int tid = threadIdx.x;
    if (tid < BM) toks[tid] = g_token_list[slot0 + tid];
    __syncthreads();

    int lane = tid & 31;
    int wid  = tid >> 5;
    int wm = wid & 1;        // 2 warp rows  (32 M each)
    int wn = wid >> 1;       // 4 warp cols  (32 N each)
    int gr = lane >> 2;      // fragment group row (0..7)
    int gc = lane & 3;       // fragment group col (0..3)

    int am = tid >> 4, ak = tid & 15;
    int br0 = tid >> 7, bc = tid & 127;

    float rA[4], rB1[8], rB2[8];
    float C1[2][4][4], C2[2][4][4];
#pragma unroll
    for (int mi = 0; mi < 2; mi++)
#pragma unroll
        for (int ni = 0; ni < 4; ni++)
#pragma unroll
            for (int q = 0; q < 4; q++) { C1[mi][ni][q] = 0.f; C2[mi][ni][q] = 0.f; }

    // prologue: load k0=0 tile
#pragma unroll
    for (int i = 0; i < 4; i++) {
        int t = toks[am + i * 16];
        rA[i] = (t >= 0) ? x[(size_t)t * DD + ak] : 0.f;
    }
#pragma unroll
    for (int i = 0; i < 8; i++) {
        int r = br0 + i * 2;
        size_t g = (size_t)r * DH + n0 + bc;
        rB1[i] = B1[g];
        rB2[i] = B2[g];
    }
#pragma unroll
    for (int i = 0; i < 4; i++) As[0][ak][am + i * 16] = rA[i];
#pragma unroll
    for (int i = 0; i < 8; i++) { Bs1[0][br0 + i * 2][bc] = rB1[i]; Bs2[0][br0 + i * 2][bc] = rB2[i]; }
    __syncthreads();

    int buf = 0;
    for (int k0 = 0; k0 < DD; k0 += BK) {
        bool has_next = (k0 + BK) < DD;
        if (has_next) {
            int kn = k0 + BK;
#pragma unroll
            for (int i = 0; i < 4; i++) {
                int t = toks[am + i * 16];
                rA[i] = (t >= 0) ? x[(size_t)t * DD + kn + ak] : 0.f;
            }
#pragma unroll
            for (int i = 0; i < 8; i++) {
                int r = br0 + i * 2;
                size_t g = (size_t)(kn + r) * DH + n0 + bc;
                rB1[i] = B1[g];
                rB2[i] = B2[g];
            }
        }
        // one m16n8k16 k-step covers the whole BK=16 chunk
        {
            uint32_t ahi[2][4], alo[2][4];
#pragma unroll
            for (int mi = 0; mi < 2; mi++) {
                int mb = wm * 32 + mi * 16;
                int m0 = mb + gr, m1 = mb + gr + 8;
                split_bf16x2(As[buf][2*gc  ][m0], As[buf][2*gc+1][m0], ahi[mi][0], alo[mi][0]);
                split_bf16x2(As[buf][2*gc  ][m1], As[buf][2*gc+1][m1], ahi[mi][1], alo[mi][1]);
                split_bf16x2(As[buf][2*gc+8][m0], As[buf][2*gc+9][m0], ahi[mi][2], alo[mi][2]);
                split_bf16x2(As[buf][2*gc+8][m1], As[buf][2*gc+9][m1], ahi[mi][3], alo[mi][3]);
            }
            {
                uint32_t bh[4][2], bl[4][2];
#pragma unroll
                for (int ni = 0; ni < 4; ni++) {
                    int nn = wn * 32 + ni * 8 + gr;
                    split_bf16x2(Bs1[buf][2*gc  ][nn], Bs1[buf][2*gc+1][nn], bh[ni][0], bl[ni][0]);
                    split_bf16x2(Bs1[buf][2*gc+8][nn], Bs1[buf][2*gc+9][nn], bh[ni][1], bl[ni][1]);
                }
#pragma unroll
                for (int mi = 0; mi < 2; mi++)
#pragma unroll
                    for (int ni = 0; ni < 4; ni++) {
                        mma_bf16(C1[mi][ni], ahi[mi], bh[ni]);
                        mma_bf16(C1[mi][ni], ahi[mi], bl[ni]);
                        mma_bf16(C1[mi][ni], alo[mi], bh[ni]);
                    }
            }
            {
                uint32_t bh[4][2], bl[4][2];
#pragma unroll
                for (int ni = 0; ni < 4; ni++) {
                    int nn = wn * 32 + ni * 8 + gr;
                    split_bf16x2(Bs2[buf][2*gc  ][nn], Bs2[buf][2*gc+1][nn], bh[ni][0], bl[ni][0]);
                    split_bf16x2(Bs2[buf][2*gc+8][nn], Bs2[buf][2*gc+9][nn], bh[ni][1], bl[ni][1]);
                }
#pragma unroll
                for (int mi = 0; mi < 2; mi++)
#pragma unroll
                    for (int ni = 0; ni < 4; ni++) {
                        mma_bf16(C2[mi][ni], ahi[mi], bh[ni]);
                        mma_bf16(C2[mi][ni], ahi[mi], bl[ni]);
                        mma_bf16(C2[mi][ni], alo[mi], bh[ni]);
                    }
            }
        }
        if (has_next) {
            int nb = buf ^ 1;
#pragma unroll
            for (int i = 0; i < 4; i++) As[nb][ak][am + i * 16] = rA[i];
#pragma unroll
            for (int i = 0; i < 8; i++) { Bs1[nb][br0 + i * 2][bc] = rB1[i]; Bs2[nb][br0 + i * 2][bc] = rB2[i]; }
            __syncthreads();
            buf = nb;
        }
    }
    // epilogue: silu(c1)*c2 -> g_G
#pragma unroll
    for (int mi = 0; mi < 2; mi++)
#pragma unroll
        for (int ni = 0; ni < 4; ni++) {
            int r0 = slot0 + wm * 32 + mi * 16 + gr;
            int cb = n0 + wn * 32 + ni * 8 + gc * 2;
            float* c1 = C1[mi][ni];
            float* c2 = C2[mi][ni];
            float s0 = c1[0] / (1.f + expf(-c1[0]));
            float s1 = c1[1] / (1.f + expf(-c1[1]));
            float s2 = c1[2] / (1.f + expf(-c1[2]));
            float s3 = c1[3] / (1.f + expf(-c1[3]));
            g_G[(size_t)r0 * DH + cb]           = s0 * c2[0];
            g_G[(size_t)r0 * DH + cb + 1]       = s1 * c2[1];
            g_G[(size_t)(r0 + 8) * DH + cb]     = s2 * c2[2];
            g_G[(size_t)(r0 + 8) * DH + cb + 1] = s3 * c2[3];
        }
}

// ---------------- GEMM2: O = G @ W3  (same structure, single B) -------------
__global__ __launch_bounds__(256) void gemm2_kernel(const float* __restrict__ w3) {
    int tile_m = blockIdx.y;
    if (tile_m >= g_num_mtiles) return;
    int e = g_tile_expert[tile_m];
    int slot0 = tile_m * BM;
    int n0 = blockIdx.x * BN;
    const float* Bw = w3 + (size_t)e * DH * DD;

    __shared__ float As[2][BK][BMP];
    __shared__ float Bs[2][BK][BNP];

    int tid = threadIdx.x;
    int lane = tid & 31;
    int wid  = tid >> 5;
    int wm = wid & 1;
    int wn = wid >> 1;
    int gr = lane >> 2;
    int gc = lane & 3;
    int am = tid >> 4, ak = tid & 15;
    int br0 = tid >> 7, bc = tid & 127;

    float rA[4], rB[8];
    float C[2][4][4];
#pragma unroll
    for (int mi = 0; mi < 2; mi++)
#pragma unroll
        for (int ni = 0; ni < 4; ni++)
#pragma unroll
            for (int q = 0; q < 4; q++) C[mi][ni][q] = 0.f;

    // prologue
#pragma unroll
    for (int i = 0; i < 4; i++)
        rA[i] = g_G[(size_t)(slot0 + am + i * 16) * DH + ak];
#pragma unroll
    for (int i = 0; i < 8; i++) {
        int r = br0 + i * 2;
        rB[i] = Bw[(size_t)r * DD + n0 + bc];
    }
#pragma unroll
    for (int i = 0; i < 4; i++) As[0][ak][am + i * 16] = rA[i];
#pragma unroll
    for (int i = 0; i < 8; i++) Bs[0][br0 + i * 2][bc] = rB[i];
    __syncthreads();

    int buf = 0;
    for (int k0 = 0; k0 < DH; k0 += BK) {
        bool has_next = (k0 + BK) < DH;
        if (has_next) {
            int kn = k0 + BK;
#pragma unroll
            for (int i = 0; i < 4; i++)
                rA[i] = g_G[(size_t)(slot0 + am + i * 16) * DH + kn + ak];
#pragma unroll
            for (int i = 0; i < 8; i++) {
                int r = br0 + i * 2;
                rB[i] = Bw[(size_t)(kn + r) * DD + n0 + bc];
            }
        }
        {
            uint32_t ahi[2][4], alo[2][4];
#pragma unroll
            for (int mi = 0; mi < 2; mi++) {
                int mb = wm * 32 + mi * 16;
                int m0 = mb + gr, m1 = mb + gr + 8;
                split_bf16x2(As[buf][2*gc  ][m0], As[buf][2*gc+1][m0], ahi[mi][0], alo[mi][0]);
                split_bf16x2(As[buf][2*gc  ][m1], As[buf][2*gc+1][m1], ahi[mi][1], alo[mi][1]);
                split_bf16x2(As[buf][2*gc+8][m0], As[buf][2*gc+9][m0], ahi[mi][2], alo[mi][2]);
                split_bf16x2(As[buf][2*gc+8][m1], As[buf][2*gc+9][m1], ahi[mi][3], alo[mi][3]);
            }
            uint32_t bh[4][2], bl[4][2];
#pragma unroll
            for (int ni = 0; ni < 4; ni++) {
                int nn = wn * 32 + ni * 8 + gr;
                split_bf16x2(Bs[buf][2*gc  ][nn], Bs[buf][2*gc+1][nn], bh[ni][0], bl[ni][0]);
                split_bf16x2(Bs[buf][2*gc+8][nn], Bs[buf][2*gc+9][nn], bh[ni][1], bl[ni][1]);
            }
#pragma unroll
            for (int mi = 0; mi < 2; mi++)
#pragma unroll
                for (int ni = 0; ni < 4; ni++) {
                    mma_bf16(C[mi][ni], ahi[mi], bh[ni]);
                    mma_bf16(C[mi][ni], ahi[mi], bl[ni]);
                    mma_bf16(C[mi][ni], alo[mi], bh[ni]);
                }
        }
        if (has_next) {
            int nb = buf ^ 1;
#pragma unroll
            for (int i = 0; i < 4; i++) As[nb][ak][am + i * 16] = rA[i];
#pragma unroll
            for (int i = 0; i < 8; i++) Bs[nb][br0 + i * 2][bc] = rB[i];
            __syncthreads();
            buf = nb;
        }
    }
#pragma unroll
    for (int mi = 0; mi < 2; mi++)
#pragma unroll
        for (int ni = 0; ni < 4; ni++) {
            int r0 = slot0 + wm * 32 + mi * 16 + gr;
            int cb = n0 + wn * 32 + ni * 8 + gc * 2;
            float* c = C[mi][ni];
            g_O[(size_t)r0 * DD + cb]           = c[0];
            g_O[(size_t)r0 * DD + cb + 1]       = c[1];
            g_O[(size_t)(r0 + 8) * DD + cb]     = c[2];
            g_O[(size_t)(r0 + 8) * DD + cb + 1] = c[3];
        }
}

// ---------------- combine (atomic-free, deterministic) ----------------------
__global__ void combine_kernel(float* __restrict__ out) {
    size_t i = (size_t)blockIdx.x * blockDim.x + threadIdx.x;
    const size_t total4 = (size_t)DT * DD / 4;
    if (i >= total4) return;
    int t = (int)(i / (DD / 4));
    int dg = (int)(i % (DD / 4));
    int r0 = g_rowof[t * 2 + 0], r1 = g_rowof[t * 2 + 1];
    float w0 = g_topw[t * 2 + 0], w1 = g_topw[t * 2 + 1];
    float4 a = reinterpret_cast<const float4*>(g_O + (size_t)r0 * DD)[dg];
    float4 b = reinterpret_cast<const float4*>(g_O + (size_t)r1 * DD)[dg];
    float4 o;
    o.x = w0 * a.x + w1 * b.x;
    o.y = w0 * a.y + w1 * b.y;
    o.z = w0 * a.z + w1 * b.z;
    o.w = w0 * a.w + w1 * b.w;
    reinterpret_cast<float4*>(out)[i] = o;
}

// ---------------- SPR prep: gather + row-normalize x and probs rows ---------
__global__ __launch_bounds__(256) void spr_prep_kernel(
    const float* __restrict__ x, IdxArr idx) {
    int i = blockIdx.x;           // 0..255 subsampled row
    int t = idx.v[i];
    const float* xr = x + (size_t)t * DD;
    __shared__ float sm[256];
    __shared__ float s_inv;
    float s = 0.f;
    for (int k = threadIdx.x; k < DD; k += 256) { float v = xr[k]; s += v * v; }
    sm[threadIdx.x] = s;
    __syncthreads();
    for (int o = 128; o > 0; o >>= 1) {
        if (threadIdx.x < o) sm[threadIdx.x] += sm[threadIdx.x + o];
        __syncthreads();
    }
    if (threadIdx.x == 0) {
        s_inv = 1.f / fmaxf(sqrtf(sm[0]), 1e-12f);
        float pr[DE], ps = 0.f;
#pragma unroll
        for (int e = 0; e < DE; e++) { pr[e] = g_probs[t * DE + e]; ps += pr[e] * pr[e]; }
        float pinv = 1.f / fmaxf(sqrtf(ps), 1e-12f);
#pragma unroll
        for (int e = 0; e < DE; e++) g_rn[i * DE + e] = pr[e] * pinv;
    }
    __syncthreads();
    float inv = s_inv;
    for (int k = threadIdx.x; k < DD; k += 256) g_xn[(size_t)i * DD + k] = xr[k] * inv;
}

// ---------------- SPR gram diff: block i computes row i of both grams -------
__global__ __launch_bounds__(256) void spr_gram_kernel() {
    int i = blockIdx.x;           // 0..255
    __shared__ float xi[DD];      // 8 KB
    __shared__ float ri[DE];
    __shared__ float sm[256];
    for (int k = threadIdx.x; k < DD; k += 256) xi[k] = g_xn[(size_t)i * DD + k];
    if (threadIdx.x < DE) ri[threadIdx.x] = g_rn[i * DE + threadIdx.x];
    __syncthreads();
    int j = threadIdx.x;
    float dx = 0.f;
    const float* xj = g_xn + (size_t)j * DD;
    for (int k = 0; k < DD; k++) dx += xi[k] * xj[k];
    float dr = 0.f;
#pragma unroll
    for (int e = 0; e < DE; e++) dr += ri[e] * g_rn[j * DE + e];
    float d = dr - dx;
    sm[threadIdx.x] = d * d;
    __syncthreads();
    for (int o = 128; o > 0; o >>= 1) {
        if (threadIdx.x < o) sm[threadIdx.x] += sm[threadIdx.x + o];
        __syncthreads();
    }
    if (threadIdx.x == 0) g_spr_part[i] = sm[0];
}

// ---------------- aux loss: load_balance + dpsl + 0.1*spr -------------------
__global__ void aux_kernel(float* __restrict__ out, int out_size) {
    if (threadIdx.x == 0 && blockIdx.x == 0) {
        float lb = 0.f, dpsl = 0.f;
        const float prior = 0.125f;
        const float logp  = logf(prior);
        for (int e = 0; e < DE; e++) {
            float f = (float)g_counts[e] / (float)(DT * KTOP);
            float P = g_Psum[e] / (float)DT;
            lb += f * P;
            dpsl += prior * (logp - logf(P));
        }
        lb *= (float)DE;
        float sprs = 0.f;
        for (int i = 0; i < NSPR; i++) sprs += g_spr_part[i];
        float spr = sprs / (float)(NSPR * NSPR);
        float aux = 0.01f * (lb + dpsl + 0.1f * spr);
        for (size_t i = (size_t)DT * DD; i < (size_t)out_size; i++) out[i] = aux;
    }
}

// ============================================================================
// Host-side replication of jax.random.permutation(jax.random.key(123), 8192)
// Input-independent: runs once at graph-capture time, zero cost in replays.
// ============================================================================
static inline uint32_t rotl32h(uint32_t x, int r) { return (x << r) | (x >> (32 - r)); }

static void threefry2x32_host(uint32_t k1, uint32_t k2, uint32_t x1, uint32_t x2,
                              uint32_t* o1, uint32_t* o2) {
    uint32_t ks0 = k1, ks1 = k2, ks2 = k1 ^ k2 ^ 0x1BD11BDAu;
    uint32_t ks[3] = {ks0, ks1, ks2};
    uint32_t a = x1 + ks0, b = x2 + ks1;
    static const int R[2][4] = {{13, 15, 26, 6}, {17, 29, 16, 24}};
    for (int i = 0; i < 5; i++) {
        const int* r = R[i & 1];
        for (int j = 0; j < 4; j++) { a += b; b = rotl32h(b, r[j]); b ^= a; }
        a += ks[(i + 1) % 3];
        b += ks[(i + 2) % 3] + (uint32_t)(i + 1);
    }
    *o1 = a; *o2 = b;
}

// split(key) -> (new_key, subkey): threefry on counts [0,1,2,3] paired (0,2),(1,3)
static void jax_split_host(const uint32_t key[2], uint32_t newkey[2], uint32_t subkey[2]) {
    uint32_t a0, b0, a1, b1;
    threefry2x32_host(key[0], key[1], 0u, 2u, &a0, &b0);
    threefry2x32_host(key[0], key[1], 1u, 3u, &a1, &b1);
    newkey[0] = a0; newkey[1] = a1;
    subkey[0] = b0; subkey[1] = b1;
}

static void compute_spr_indices(int* idx_out) {
    const int T = DT;             // 8192
    static uint32_t bits[DT];
    static int vals[DT];
    static int order[DT];
    static int tmp[DT];
    for (int i = 0; i < T; i++) vals[i] = i;

    uint32_t key[2] = {0u, 123u};     // jax.random.key(123) -> (0, 123)
    for (int round = 0; round < 2; round++) {   // num_rounds = 2 for T=8192
        uint32_t nk[2], sk[2];
        jax_split_host(key, nk, sk);
        key[0] = nk[0]; key[1] = nk[1];
        // random_bits(subkey, 32, (8192,)): pairs (i, i+4096)
        for (int i = 0; i < T / 2; i++) {
            uint32_t o1, o2;
            threefry2x32_host(sk[0], sk[1], (uint32_t)i, (uint32_t)(i + T / 2), &o1, &o2);
            bits[i] = o1;
            bits[i + T / 2] = o2;
        }
        // stable sort by bits, carrying vals (matches lax.sort_key_val)
        for (int i = 0; i < T; i++) order[i] = i;
        std::stable_sort(order, order + T,
                         [](int a, int b) { return bits[a] < bits[b]; });
        for (int i = 0; i < T; i++) tmp[i] = vals[order[i]];
        for (int i = 0; i < T; i++) vals[i] = tmp[i];
    }
    for (int i = 0; i < NSPR; i++) idx_out[i] = vals[i];
}

// ---------------- launch ----------------------------------------------------
extern "C" void kernel_launch(void* const* d_in, const int* in_sizes, int n_in,
                              void* d_out, int out_size) {
    const float* x  = (const float*)d_in[0];
    const float* gw = (const float*)d_in[1];
    const float* w1 = (const float*)d_in[2];
    const float* w2 = (const float*)d_in[3];
    const float* w3 = (const float*)d_in[4];
    float* out = (float*)d_out;

    IdxArr idx;
    compute_spr_indices(idx.v);   // pure host compute; deterministic

    reset_kernel<<<(MAXSLOT + 255) / 256, 256>>>();         // idx 0
    router_kernel<<<DT / 8, 256>>>(x, gw);                  // idx 1
    assign_plan_kernel<<<(DT + 255) / 256, 256>>>();        // idx 2

    dim3 g1(DH / BN, MAXMT);     // 44 x 264
    gemm1_kernel<<<g1, 256>>>(x, w1, w2);                   // idx 3 (profiler target)
    dim3 g2(DD / BN, MAXMT);     // 16 x 264
    gemm2_kernel<<<g2, 256>>>(w3);                          // idx 4

    const size_t total4 = (size_t)DT * DD / 4;
    combine_kernel<<<(unsigned)((total4 + 255) / 256), 256>>>(out);

    preduce_kernel<<<DE, 256>>>();
    spr_prep_kernel<<<NSPR, 256>>>(x, idx);
    spr_gram_kernel<<<NSPR, 256>>>();
    aux_kernel<<<1, 32>>>(out, out_size);
}